// round 12
// baseline (speedup 1.0000x reference)
#include <cuda_runtime.h>
#include <cstdint>

// Tile-gather gaussian splatting into 256^3.
//  prep:  per-gaussian padded separable weight tables + per-(gaussian,tile)
//         records carrying fully precomputed g_w float-offsets
//  splat: 16^3 tiles, thread owns 8 z; SMEM-staged weight slices + compact
//         per-x-column hit lists (built during staging) -> branch-free inner
//         loop of pure LDS + packed f32x2 FFMA over only the full hits.
//         No volume atomics, no memset; self-resets tile counts.
//
// inputs (metadata order): centers [N,3] f32, sigmas [N] f32, intensities [N] f32
// output: 256^3 f32

#define NMAX    5008
#define TILES   4096      // 16^3 tiles of 16^3 voxels
#define MAXPER  64        // records per tile (avg ~10)
#define WSTRIDE 192       // per-gaussian weights: x[64] | y[64] | z[48]+pad[16]

__device__ int   g_count[TILES];          // zero at load; splat self-resets
__device__ uint4 g_list[TILES * MAXPER];  // {xaddr, yaddr, zaddr, 0} float offsets into g_w
__device__ __align__(16) float g_w[NMAX * WSTRIDE];

// packed f32x2 helpers (sm_103a; ptxas never auto-fuses FFMA2 from C++)
#define PACK_DUP_F32X2(out, v) \
    asm("mov.b64 %0, {%1, %1};" : "=l"(out) : "r"(__float_as_uint(v)))
#define FMA_F32X2(d, a, b, c) \
    asm("fma.rn.f32x2 %0, %1, %2, %3;" : "=l"(d) : "l"(a), "l"(b), "l"(c))

__global__ __launch_bounds__(192)
void prep_kernel(const float* __restrict__ centers,
                 const float* __restrict__ sigmas,
                 const float* __restrict__ intens,
                 int n)
{
    const int g = blockIdx.x;
    if (g >= n) return;

    __shared__ int s_lo[3], s_hi[3];

    const float sig = sigmas[g];
    const bool  act = (sig > 0.0f);
    const int   t   = threadIdx.x;

    const float inv2s2 = act ? 0.5f / (sig * sig) : 0.0f;
    const float cut    = 3.0f * sig * 255.0f;

    // ----- weight table entry for this thread -----
    const int   ax = t >> 6;                  // 0:x 1:y 2:z
    const float c  = centers[3 * g + ax];
    const float cv = c * 255.0f;
    // reference trunc semantics
    const int lo = (int)fmaxf(cv - cut, 0.0f);
    const int hi = min((int)(fminf(cv + cut, 255.0f) + 1.0f), 256);
    const int wd = hi - lo;                   // in [1,26]

    if ((t & 63) == 0) { s_lo[ax] = lo; s_hi[ax] = hi; }

    float val = 0.0f;
    if (act) {
        int  idx;
        bool v;
        if (ax < 2) {                         // x/y: offsets -16..47, zero-padded
            const int off = (t & 63) - 16;
            idx = lo + off;
            v   = (off >= 0) && (off < wd);
        } else {                              // z: absolute grid from (lo & ~15)
            const int e = t - 128;            // 0..63
            idx = (lo & ~15) + e;
            v   = (e < 48) && (idx >= lo) && (idx < hi);
        }
        if (v) {
            const float d = (float)idx * (1.0f / 255.0f) - c;
            val = __expf(-d * d * inv2s2);
            if (ax == 0) val *= intens[g];    // fold intensity into x
        }
    }
    g_w[g * WSTRIDE + t] = val;
    __syncthreads();

    // ----- tile binning: <=27 tiles, one thread each -----
    if (act && t < 27) {
        const int x0 = s_lo[0], y0 = s_lo[1], z0 = s_lo[2];
        const int tx0 = x0 >> 4, ty0 = y0 >> 4, tz0 = z0 >> 4;
        const int nx  = ((s_hi[0] - 1) >> 4) - tx0 + 1;
        const int ny  = ((s_hi[1] - 1) >> 4) - ty0 + 1;
        const int nz  = ((s_hi[2] - 1) >> 4) - tz0 + 1;   // each in [1,3]
        if (t < nx * ny * nz) {
            const int a   = t / (ny * nz);
            const int rem = t - a * (ny * nz);
            const int b   = rem / nz;
            const int cq  = rem - b * nz;
            const int tx = tx0 + a, ty = ty0 + b, tz = tz0 + cq;
            const int tile = (tx << 8) | (ty << 4) | tz;

            const unsigned base = (unsigned)g * WSTRIDE;
            const unsigned rx = base + (unsigned)(16 + (tx << 4) - x0);           // x table
            const unsigned ry = base + 64u + (unsigned)(16 + (ty << 4) - y0);     // y table
            const unsigned rz = base + 128u + (unsigned)((tz << 4) - (z0 & ~15)); // z table

            const int pos = atomicAdd(&g_count[tile], 1);
            if (pos < MAXPER)
                g_list[tile * MAXPER + pos] = make_uint4(rx, ry, rz, 0u);
        }
    }
}

// 512 threads: thread owns 8 consecutive z of one (x,y) column.
//   xloc = tid>>5  (uniform per warp -> per-warp compact hit list)
//   yloc = (tid>>1)&15, zh = tid&1 (z offset 0 or 8)
__global__ __launch_bounds__(512)
void splat_kernel(float* __restrict__ vol)
{
    const int tile = blockIdx.x;
    const int tid  = threadIdx.x;

    const int tx = tile >> 8, ty = (tile >> 4) & 15, tz = tile & 15;
    const int xloc = tid >> 5;
    const int yloc = (tid >> 1) & 15;
    const int zh   = tid & 1;

    // staged weight slices: 16 floats per hit per axis
    __shared__ __align__(16) float s_x[MAXPER * 16];
    __shared__ __align__(16) float s_y[MAXPER * 16];
    __shared__ __align__(16) float s_z[MAXPER * 16];
    // per-x-column compact lists of full hits (values are h<<4)
    __shared__ int s_cnt[16];
    __shared__ int s_hlist[16 * MAXPER];

    const int hits = min(g_count[tile], MAXPER);

    if (tid < 16) s_cnt[tid] = 0;
    __syncthreads();
    if (tid == 0) g_count[tile] = 0;      // all threads read it above; self-reset

    // stage all hit weight slices (coalesced; <=2 rounds at 512 threads) and
    // build per-xloc full-hit lists from the x values as they stream through.
    for (int i = tid; i < (hits << 4); i += 512) {
        const int h = i >> 4;
        const int j = i & 15;
        const uint4 r = g_list[tile * MAXPER + h];
        const float vx = g_w[r.x + j];
        s_x[i] = vx;
        s_y[i] = g_w[r.y + j];
        s_z[i] = g_w[r.z + j];
        if (vx != 0.0f) {                  // this gaussian touches column j
            const int p = atomicAdd(&s_cnt[j], 1);
            s_hlist[j * MAXPER + p] = i - j;   // = h << 4
        }
    }
    __syncthreads();

    // accumulators as 4x f32x2 pairs (z0|z1, z2|z3, z4|z5, z6|z7)
    unsigned long long acc01 = 0ull, acc23 = 0ull, acc45 = 0ull, acc67 = 0ull;

    // branch-free inner loop over this warp's full hits only: LDS + FFMA2
    const int  nh  = s_cnt[xloc];
    const int* lst = &s_hlist[xloc * MAXPER];
    #pragma unroll 2
    for (int k = 0; k < nh; k++) {
        const int hb = lst[k];                     // broadcast LDS
        const float wx  = s_x[hb + xloc];          // broadcast, nonzero
        const float wy  = s_y[hb + yloc];          // zero-padded: OOW -> 0
        const float wxy = wx * wy;
        unsigned long long wxy2;
        PACK_DUP_F32X2(wxy2, wxy);

        const ulonglong2* __restrict__ wz =
            reinterpret_cast<const ulonglong2*>(&s_z[hb + (zh << 3)]);
        const ulonglong2 za = wz[0];
        const ulonglong2 zb = wz[1];

        FMA_F32X2(acc01, za.x, wxy2, acc01);
        FMA_F32X2(acc23, za.y, wxy2, acc23);
        FMA_F32X2(acc45, zb.x, wxy2, acc45);
        FMA_F32X2(acc67, zb.y, wxy2, acc67);
    }

    // Exclusive tile ownership: vectorized stores (same bits as float4).
    const int x = (tx << 4) + xloc;
    const int y = (ty << 4) + yloc;
    ulonglong2* out = reinterpret_cast<ulonglong2*>(
        vol + (((x << 8) + y) << 8) + (tz << 4) + (zh << 3));
    out[0] = make_ulonglong2(acc01, acc23);
    out[1] = make_ulonglong2(acc45, acc67);
}

extern "C" void kernel_launch(void* const* d_in, const int* in_sizes, int n_in,
                              void* d_out, int out_size)
{
    const float* centers = (const float*)d_in[0];
    const float* sigmas  = (const float*)d_in[1];
    const float* intens  = (const float*)d_in[2];
    float* vol = (float*)d_out;

    int n = in_sizes[1];                 // sigmas element count = N
    if (n > NMAX) n = NMAX;

    if (n > 0) prep_kernel<<<n, 192>>>(centers, sigmas, intens, n);
    splat_kernel<<<TILES, 512>>>(vol);
}

// round 13
// speedup vs baseline: 1.5500x; 1.5500x over previous
#include <cuda_runtime.h>
#include <cstdint>

// Tile-gather gaussian splatting into 256^3.
//  prep:  per-gaussian padded separable weight tables + per-(gaussian,tile)
//         records carrying fully precomputed g_w float-offsets
//  splat: 16^3 tiles, thread owns 8 z; SMEM-staged weight slices, global-free
//         inner loop (LDS + packed f32x2 FFMA), warp-uniform x-skip with the
//         skip predicate software-pipelined one hit ahead.
//         No volume atomics, no memset; self-resets tile counts.
//
// inputs (metadata order): centers [N,3] f32, sigmas [N] f32, intensities [N] f32
// output: 256^3 f32

#define NMAX    5008
#define TILES   4096      // 16^3 tiles of 16^3 voxels
#define MAXPER  64        // records per tile (avg ~10)
#define WSTRIDE 192       // per-gaussian weights: x[64] | y[64] | z[48]+pad[16]

__device__ int   g_count[TILES];          // zero at load; splat self-resets
__device__ uint4 g_list[TILES * MAXPER];  // {xaddr, yaddr, zaddr, 0} float offsets into g_w
__device__ __align__(16) float g_w[NMAX * WSTRIDE];

// packed f32x2 helpers (sm_103a; ptxas never auto-fuses FFMA2 from C++)
#define PACK_DUP_F32X2(out, v) \
    asm("mov.b64 %0, {%1, %1};" : "=l"(out) : "r"(__float_as_uint(v)))
#define FMA_F32X2(d, a, b, c) \
    asm("fma.rn.f32x2 %0, %1, %2, %3;" : "=l"(d) : "l"(a), "l"(b), "l"(c))

__global__ __launch_bounds__(192)
void prep_kernel(const float* __restrict__ centers,
                 const float* __restrict__ sigmas,
                 const float* __restrict__ intens,
                 int n)
{
    const int g = blockIdx.x;
    if (g >= n) return;

    __shared__ int s_lo[3], s_hi[3];

    const float sig = sigmas[g];
    const bool  act = (sig > 0.0f);
    const int   t   = threadIdx.x;

    const float inv2s2 = act ? 0.5f / (sig * sig) : 0.0f;
    const float cut    = 3.0f * sig * 255.0f;

    // ----- weight table entry for this thread -----
    const int   ax = t >> 6;                  // 0:x 1:y 2:z
    const float c  = centers[3 * g + ax];
    const float cv = c * 255.0f;
    // reference trunc semantics
    const int lo = (int)fmaxf(cv - cut, 0.0f);
    const int hi = min((int)(fminf(cv + cut, 255.0f) + 1.0f), 256);
    const int wd = hi - lo;                   // in [1,26]

    if ((t & 63) == 0) { s_lo[ax] = lo; s_hi[ax] = hi; }

    float val = 0.0f;
    if (act) {
        int  idx;
        bool v;
        if (ax < 2) {                         // x/y: offsets -16..47, zero-padded
            const int off = (t & 63) - 16;
            idx = lo + off;
            v   = (off >= 0) && (off < wd);
        } else {                              // z: absolute grid from (lo & ~15)
            const int e = t - 128;            // 0..63
            idx = (lo & ~15) + e;
            v   = (e < 48) && (idx >= lo) && (idx < hi);
        }
        if (v) {
            const float d = (float)idx * (1.0f / 255.0f) - c;
            val = __expf(-d * d * inv2s2);
            if (ax == 0) val *= intens[g];    // fold intensity into x
        }
    }
    g_w[g * WSTRIDE + t] = val;
    __syncthreads();

    // ----- tile binning: <=27 tiles, one thread each -----
    if (act && t < 27) {
        const int x0 = s_lo[0], y0 = s_lo[1], z0 = s_lo[2];
        const int tx0 = x0 >> 4, ty0 = y0 >> 4, tz0 = z0 >> 4;
        const int nx  = ((s_hi[0] - 1) >> 4) - tx0 + 1;
        const int ny  = ((s_hi[1] - 1) >> 4) - ty0 + 1;
        const int nz  = ((s_hi[2] - 1) >> 4) - tz0 + 1;   // each in [1,3]
        if (t < nx * ny * nz) {
            const int a   = t / (ny * nz);
            const int rem = t - a * (ny * nz);
            const int b   = rem / nz;
            const int cq  = rem - b * nz;
            const int tx = tx0 + a, ty = ty0 + b, tz = tz0 + cq;
            const int tile = (tx << 8) | (ty << 4) | tz;

            const unsigned base = (unsigned)g * WSTRIDE;
            const unsigned rx = base + (unsigned)(16 + (tx << 4) - x0);           // x table
            const unsigned ry = base + 64u + (unsigned)(16 + (ty << 4) - y0);     // y table
            const unsigned rz = base + 128u + (unsigned)((tz << 4) - (z0 & ~15)); // z table

            const int pos = atomicAdd(&g_count[tile], 1);
            if (pos < MAXPER)
                g_list[tile * MAXPER + pos] = make_uint4(rx, ry, rz, 0u);
        }
    }
}

// 512 threads: thread owns 8 consecutive z of one (x,y) column.
//   xloc = tid>>5  (uniform per warp -> warp-uniform x-skip)
//   yloc = (tid>>1)&15, zh = tid&1 (z offset 0 or 8)
__global__ __launch_bounds__(512)
void splat_kernel(float* __restrict__ vol)
{
    const int tile = blockIdx.x;
    const int tid  = threadIdx.x;

    const int tx = tile >> 8, ty = (tile >> 4) & 15, tz = tile & 15;
    const int xloc = tid >> 5;
    const int yloc = (tid >> 1) & 15;
    const int zh   = tid & 1;

    // staged weight slices: 16 floats per hit per axis
    // s_x has one extra 16-float row so the h+1 prefetch at h=hits-1 is in-bounds
    __shared__ __align__(16) float s_x[(MAXPER + 1) * 16];
    __shared__ __align__(16) float s_y[MAXPER * 16];
    __shared__ __align__(16) float s_z[MAXPER * 16];

    const int hits = min(g_count[tile], MAXPER);

    // stage all hit weight slices (coalesced; <=2 rounds at 512 threads)
    for (int i = tid; i < (hits << 4); i += 512) {
        const int h = i >> 4;
        const int j = i & 15;
        const uint4 r = g_list[tile * MAXPER + h];
        s_x[i] = g_w[r.x + j];
        s_y[i] = g_w[r.y + j];
        s_z[i] = g_w[r.z + j];
    }
    __syncthreads();
    if (tid == 0) g_count[tile] = 0;      // self-reset for next graph replay

    // accumulators as 4x f32x2 pairs (z0|z1, z2|z3, z4|z5, z6|z7)
    unsigned long long acc01 = 0ull, acc23 = 0ull, acc45 = 0ull, acc67 = 0ull;

    // global-free inner loop: LDS + packed FFMA2.
    // wx (the warp-uniform skip predicate source) is prefetched one hit ahead,
    // so the branch at iteration h never waits on shared-memory latency.
    float wx_cur = (hits > 0) ? s_x[xloc] : 0.0f;

    #pragma unroll 2
    for (int h = 0; h < hits; h++) {
        const int hb = h << 4;
        const float wx_next = s_x[hb + 16 + xloc];   // safe: padded row

        // warp-uniform skip: ~half of (warp,hit) pairs are out-of-window in x
        if (wx_cur != 0.0f) {
            const float wy  = s_y[hb + yloc];        // zero-padded: OOW -> 0
            const float wxy = wx_cur * wy;
            unsigned long long wxy2;
            PACK_DUP_F32X2(wxy2, wxy);

            // 8 z-weights as 4 packed f32x2 (two LDS.128 viewed as u64 pairs)
            const ulonglong2* __restrict__ wz =
                reinterpret_cast<const ulonglong2*>(&s_z[hb + (zh << 3)]);
            const ulonglong2 za = wz[0];
            const ulonglong2 zb = wz[1];

            FMA_F32X2(acc01, za.x, wxy2, acc01);
            FMA_F32X2(acc23, za.y, wxy2, acc23);
            FMA_F32X2(acc45, zb.x, wxy2, acc45);
            FMA_F32X2(acc67, zb.y, wxy2, acc67);
        }
        wx_cur = wx_next;
    }

    // Exclusive tile ownership: vectorized stores (same bits as float4).
    const int x = (tx << 4) + xloc;
    const int y = (ty << 4) + yloc;
    ulonglong2* out = reinterpret_cast<ulonglong2*>(
        vol + (((x << 8) + y) << 8) + (tz << 4) + (zh << 3));
    out[0] = make_ulonglong2(acc01, acc23);
    out[1] = make_ulonglong2(acc45, acc67);
}

extern "C" void kernel_launch(void* const* d_in, const int* in_sizes, int n_in,
                              void* d_out, int out_size)
{
    const float* centers = (const float*)d_in[0];
    const float* sigmas  = (const float*)d_in[1];
    const float* intens  = (const float*)d_in[2];
    float* vol = (float*)d_out;

    int n = in_sizes[1];                 // sigmas element count = N
    if (n > NMAX) n = NMAX;

    if (n > 0) prep_kernel<<<n, 192>>>(centers, sigmas, intens, n);
    splat_kernel<<<TILES, 512>>>(vol);
}